// round 6
// baseline (speedup 1.0000x reference)
#include <cuda_runtime.h>
#include <math.h>

// Problem constants: B=32, C=3, H=W=512
#define BB 32
#define CC 3
#define HH 512
#define WW 512
#define PX 4   // pixels per thread

// Per-batch affine 2x2 (translation exactly zero): [m00 m01 m10 m11]
__device__ float d_theta[BB][4];

__global__ void compute_theta_kernel(const float* __restrict__ thetas,
                                     const float* __restrict__ l1s,
                                     const float* __restrict__ l2s) {
    int b = threadIdx.x;
    if (b >= BB) return;
    float th = -thetas[b];
    float c = cosf(th);
    float s = sinf(th);
    float il1 = 1.0f / l1s[b];
    float il2 = 1.0f / l2s[b];
    float m00 = c * c * il1 + s * s * il2;
    float m11 = s * s * il1 + c * c * il2;
    float m01 = c * s * (il2 - il1);
    d_theta[b][0] = m00;
    d_theta[b][1] = m01;
    d_theta[b][2] = m01;
    d_theta[b][3] = m11;
}

// Each thread computes PX=4 consecutive output pixels (one float4 store / channel).
__global__ __launch_bounds__(256) void warp_kernel(const float* __restrict__ x,
                                                   float* __restrict__ out) {
    int tx = blockIdx.x * blockDim.x + threadIdx.x;   // strip index in x
    int py = blockIdx.y * blockDim.y + threadIdx.y;
    int b  = blockIdx.z;
    int px0 = tx * PX;

    float m00 = d_theta[b][0];
    float m01 = d_theta[b][1];
    float m10 = d_theta[b][2];
    float m11 = d_theta[b][3];

    // Normalized coords of first pixel center
    float X = ((float)px0 + 0.5f) * (2.0f / (float)WW) - 1.0f;
    float Y = ((float)py + 0.5f) * (2.0f / (float)HH) - 1.0f;

    // Pixel-space sample coords; per-output-pixel step is (m00, m10). m00 > 0 always.
    float gx0 = (m00 * X + m01 * Y + 1.0f) * ((float)WW * 0.5f) - 0.5f;
    float gy0 = (m10 * X + m11 * Y + 1.0f) * ((float)HH * 0.5f) - 0.5f;

    float* ob = out + ((size_t)b * CC) * HH * WW + (size_t)py * WW + px0;

    // ---- Fully-OOB strip fast path ----
    // A pixel contributes zero iff gx < -1 || gx >= W || gy < -1 || gy >= H.
    // gx increases by m00 (>0); gy changes monotonically by m10.
    {
        float gx_hi = gx0 + (PX - 1) * m00;               // gx0 is the min
        float gyA = gy0, gyB = gy0 + (PX - 1) * m10;
        float gy_lo = fminf(gyA, gyB);
        float gy_hi = fmaxf(gyA, gyB);
        if (gx_hi < -1.0f || gx0 >= (float)WW || gy_hi < -1.0f || gy_lo >= (float)HH) {
            float4 z = make_float4(0.f, 0.f, 0.f, 0.f);
#pragma unroll
            for (int c = 0; c < CC; c++)
                *(float4*)(ob + (size_t)c * HH * WW) = z;
            return;
        }
    }

    float w00[PX], w01[PX], w10[PX], w11[PX];
    int   i00[PX], i01[PX], i10[PX], i11[PX];

    float gx = gx0, gy = gy0;
#pragma unroll
    for (int k = 0; k < PX; k++) {
        float x0f = floorf(gx);
        float y0f = floorf(gy);
        int x0 = (int)x0f;
        int y0 = (int)y0f;
        int x1 = x0 + 1;
        int y1 = y0 + 1;

        float wx1 = gx - x0f;
        float wx0 = 1.0f - wx1;
        float wy1 = gy - y0f;
        float wy0 = 1.0f - wy1;

        float mx0 = (x0 >= 0 && x0 < WW) ? 1.0f : 0.0f;
        float mx1 = (x1 >= 0 && x1 < WW) ? 1.0f : 0.0f;
        float my0 = (y0 >= 0 && y0 < HH) ? 1.0f : 0.0f;
        float my1 = (y1 >= 0 && y1 < HH) ? 1.0f : 0.0f;

        w00[k] = wy0 * wx0 * my0 * mx0;
        w01[k] = wy0 * wx1 * my0 * mx1;
        w10[k] = wy1 * wx0 * my1 * mx0;
        w11[k] = wy1 * wx1 * my1 * mx1;

        int xc0 = min(max(x0, 0), WW - 1);
        int xc1 = min(max(x1, 0), WW - 1);
        int yc0 = min(max(y0, 0), HH - 1);
        int yc1 = min(max(y1, 0), HH - 1);

        i00[k] = yc0 * WW + xc0;
        i01[k] = yc0 * WW + xc1;
        i10[k] = yc1 * WW + xc0;
        i11[k] = yc1 * WW + xc1;

        gx += m00;
        gy += m10;
    }

    const float* xb = x + (size_t)b * CC * HH * WW;

#pragma unroll
    for (int c = 0; c < CC; c++) {
        const float* p = xb + (size_t)c * HH * WW;
        float v[PX];
#pragma unroll
        for (int k = 0; k < PX; k++) {
            // issue guarded loads first for MLP, then combine
            float a = (w00[k] != 0.0f) ? __ldg(p + i00[k]) : 0.0f;
            float bq = (w01[k] != 0.0f) ? __ldg(p + i01[k]) : 0.0f;
            float cq = (w10[k] != 0.0f) ? __ldg(p + i10[k]) : 0.0f;
            float dq = (w11[k] != 0.0f) ? __ldg(p + i11[k]) : 0.0f;
            v[k] = w00[k] * a + w01[k] * bq + w10[k] * cq + w11[k] * dq;
        }
        *(float4*)(ob + (size_t)c * HH * WW) = make_float4(v[0], v[1], v[2], v[3]);
    }
}

extern "C" void kernel_launch(void* const* d_in, const int* in_sizes, int n_in,
                              void* d_out, int out_size) {
    const float* x      = (const float*)d_in[0];
    const float* thetas = (const float*)d_in[1];
    const float* l1s    = (const float*)d_in[2];
    const float* l2s    = (const float*)d_in[3];
    float* out = (float*)d_out;

    compute_theta_kernel<<<1, BB>>>(thetas, l1s, l2s);

    dim3 block(32, 8, 1);                    // 32 strips * 4 px = 128 px in x
    dim3 grid(WW / (32 * PX), HH / 8, BB);   // 4 x 64 x 32
    warp_kernel<<<grid, block>>>(x, out);
}

// round 7
// speedup vs baseline: 1.6346x; 1.6346x over previous
#include <cuda_runtime.h>
#include <math.h>

// Problem constants: B=32, C=3, H=W=512
#define BB 32
#define CC 3
#define HH 512
#define WW 512
#define PX 4   // pixels per thread, warp-interleaved (stride 32)

// Per-batch affine 2x2 (translation exactly zero): [m00 m01 m10 m11]
__device__ float d_theta[BB][4];

__global__ void compute_theta_kernel(const float* __restrict__ thetas,
                                     const float* __restrict__ l1s,
                                     const float* __restrict__ l2s) {
    int b = threadIdx.x;
    if (b >= BB) return;
    float th = -thetas[b];
    float c = cosf(th);
    float s = sinf(th);
    float il1 = 1.0f / l1s[b];
    float il2 = 1.0f / l2s[b];
    float m00 = c * c * il1 + s * s * il2;
    float m11 = s * s * il1 + c * c * il2;
    float m01 = c * s * (il2 - il1);
    d_theta[b][0] = m00;
    d_theta[b][1] = m01;
    d_theta[b][2] = m01;
    d_theta[b][3] = m11;
}

// Each warp covers a 128-px x-strip of one row; thread handles pixels
// strip + lane + {0,32,64,96}. Gather LDGs have lane stride m00 px (4x
// better line locality than consecutive mapping); stores are 4 coalesced STG.32.
__global__ __launch_bounds__(256) void warp_kernel(const float* __restrict__ x,
                                                   float* __restrict__ out) {
    int lane = threadIdx.x;                           // 0..31
    int py   = blockIdx.y * blockDim.y + threadIdx.y;
    int b    = blockIdx.z;
    int px0  = blockIdx.x * (32 * PX) + lane;         // first pixel for this thread

    float m00 = d_theta[b][0];
    float m01 = d_theta[b][1];
    float m10 = d_theta[b][2];
    float m11 = d_theta[b][3];

    // Normalized coords of first pixel center
    float X = ((float)px0 + 0.5f) * (2.0f / (float)WW) - 1.0f;
    float Y = ((float)py + 0.5f) * (2.0f / (float)HH) - 1.0f;

    // Pixel-space sample coords; per-k step is 32*(m00, m10).
    float gx = (m00 * X + m01 * Y + 1.0f) * ((float)WW * 0.5f) - 0.5f;
    float gy = (m10 * X + m11 * Y + 1.0f) * ((float)HH * 0.5f) - 0.5f;
    float sx = 32.0f * m00;
    float sy = 32.0f * m10;

    float w00[PX], w01[PX], w10[PX], w11[PX];
    int   i00[PX], i01[PX], i10[PX], i11[PX];

#pragma unroll
    for (int k = 0; k < PX; k++) {
        float x0f = floorf(gx);
        float y0f = floorf(gy);
        int x0 = (int)x0f;
        int y0 = (int)y0f;
        int x1 = x0 + 1;
        int y1 = y0 + 1;

        float wx1 = gx - x0f;
        float wx0 = 1.0f - wx1;
        float wy1 = gy - y0f;
        float wy0 = 1.0f - wy1;

        float mx0 = (x0 >= 0 && x0 < WW) ? 1.0f : 0.0f;
        float mx1 = (x1 >= 0 && x1 < WW) ? 1.0f : 0.0f;
        float my0 = (y0 >= 0 && y0 < HH) ? 1.0f : 0.0f;
        float my1 = (y1 >= 0 && y1 < HH) ? 1.0f : 0.0f;

        w00[k] = wy0 * wx0 * my0 * mx0;
        w01[k] = wy0 * wx1 * my0 * mx1;
        w10[k] = wy1 * wx0 * my1 * mx0;
        w11[k] = wy1 * wx1 * my1 * mx1;

        int xc0 = min(max(x0, 0), WW - 1);
        int xc1 = min(max(x1, 0), WW - 1);
        int yc0 = min(max(y0, 0), HH - 1);
        int yc1 = min(max(y1, 0), HH - 1);

        i00[k] = yc0 * WW + xc0;
        i01[k] = yc0 * WW + xc1;
        i10[k] = yc1 * WW + xc0;
        i11[k] = yc1 * WW + xc1;

        gx += sx;
        gy += sy;
    }

    const float* xb = x + (size_t)b * CC * HH * WW;
    float* ob = out + ((size_t)b * CC) * HH * WW + (size_t)py * WW + px0;

#pragma unroll
    for (int c = 0; c < CC; c++) {
        const float* p = xb + (size_t)c * HH * WW;
        float v[PX];
#pragma unroll
        for (int k = 0; k < PX; k++) {
            float acc = 0.0f;
            if (w00[k] != 0.0f) acc += w00[k] * __ldg(p + i00[k]);
            if (w01[k] != 0.0f) acc += w01[k] * __ldg(p + i01[k]);
            if (w10[k] != 0.0f) acc += w10[k] * __ldg(p + i10[k]);
            if (w11[k] != 0.0f) acc += w11[k] * __ldg(p + i11[k]);
            v[k] = acc;
        }
        float* oc = ob + (size_t)c * HH * WW;
#pragma unroll
        for (int k = 0; k < PX; k++)
            oc[32 * k] = v[k];
    }
}

extern "C" void kernel_launch(void* const* d_in, const int* in_sizes, int n_in,
                              void* d_out, int out_size) {
    const float* x      = (const float*)d_in[0];
    const float* thetas = (const float*)d_in[1];
    const float* l1s    = (const float*)d_in[2];
    const float* l2s    = (const float*)d_in[3];
    float* out = (float*)d_out;

    compute_theta_kernel<<<1, BB>>>(thetas, l1s, l2s);

    dim3 block(32, 8, 1);                    // one warp per row-strip
    dim3 grid(WW / (32 * PX), HH / 8, BB);   // 4 x 64 x 32 = 8192 CTAs
    warp_kernel<<<grid, block>>>(x, out);
}

// round 8
// speedup vs baseline: 1.6491x; 1.0089x over previous
#include <cuda_runtime.h>
#include <math.h>

// Problem constants: B=32, C=3, H=W=512
#define BB 32
#define CC 3
#define HH 512
#define WW 512
#define PX 4   // pixels per thread, warp-interleaved (stride 32)

// Per-batch affine 2x2 (translation exactly zero): [m00 m01 m10 m11]
__device__ float d_theta[BB][4];

__global__ void compute_theta_kernel(const float* __restrict__ thetas,
                                     const float* __restrict__ l1s,
                                     const float* __restrict__ l2s) {
    int b = threadIdx.x;
    if (b >= BB) return;
    float th = -thetas[b];
    float c = cosf(th);
    float s = sinf(th);
    float il1 = 1.0f / l1s[b];
    float il2 = 1.0f / l2s[b];
    float m00 = c * c * il1 + s * s * il2;
    float m11 = s * s * il1 + c * c * il2;
    float m01 = c * s * (il2 - il1);
    d_theta[b][0] = m00;
    d_theta[b][1] = m01;
    d_theta[b][2] = m01;
    d_theta[b][3] = m11;
}

// Warp-interleaved mapping: thread handles pixels strip + lane + {0,32,64,96}.
// Guarded loads make clamping unnecessary: a load only executes when its
// weight is nonzero, which implies the raw index is in-bounds.
__global__ __launch_bounds__(256) void warp_kernel(const float* __restrict__ x,
                                                   float* __restrict__ out) {
    int lane = threadIdx.x;                           // 0..31
    int py   = blockIdx.y * blockDim.y + threadIdx.y;
    int b    = blockIdx.z;
    int px0  = blockIdx.x * (32 * PX) + lane;

    float m00 = d_theta[b][0];
    float m01 = d_theta[b][1];
    float m10 = d_theta[b][2];
    float m11 = d_theta[b][3];

    float X = ((float)px0 + 0.5f) * (2.0f / (float)WW) - 1.0f;
    float Y = ((float)py + 0.5f) * (2.0f / (float)HH) - 1.0f;

    float gx = (m00 * X + m01 * Y + 1.0f) * ((float)WW * 0.5f) - 0.5f;
    float gy = (m10 * X + m11 * Y + 1.0f) * ((float)HH * 0.5f) - 0.5f;
    float sx = 32.0f * m00;
    float sy = 32.0f * m10;

    float w00[PX], w01[PX], w10[PX], w11[PX];
    int   i00[PX];

#pragma unroll
    for (int k = 0; k < PX; k++) {
        float x0f = floorf(gx);
        float y0f = floorf(gy);
        int x0 = (int)x0f;
        int y0 = (int)y0f;

        float wx1 = gx - x0f;
        float wx0 = 1.0f - wx1;
        float wy1 = gy - y0f;
        float wy0 = 1.0f - wy1;

        // fold border masks into the 1D weights (one unsigned compare each)
        float cx0 = ((unsigned)x0       < (unsigned)WW) ? wx0 : 0.0f;
        float cx1 = ((unsigned)(x0 + 1) < (unsigned)WW) ? wx1 : 0.0f;
        float cy0 = ((unsigned)y0       < (unsigned)HH) ? wy0 : 0.0f;
        float cy1 = ((unsigned)(y0 + 1) < (unsigned)HH) ? wy1 : 0.0f;

        w00[k] = cy0 * cx0;
        w01[k] = cy0 * cx1;
        w10[k] = cy1 * cx0;
        w11[k] = cy1 * cx1;

        i00[k] = y0 * WW + x0;   // only used when the matching weight != 0

        gx += sx;
        gy += sy;
    }

    const float* xb = x + (size_t)b * CC * HH * WW;
    float* ob = out + ((size_t)b * CC) * HH * WW + (size_t)py * WW + px0;

#pragma unroll
    for (int c = 0; c < CC; c++) {
        const float* p = xb + (size_t)c * HH * WW;
        float v[PX];
#pragma unroll
        for (int k = 0; k < PX; k++) {
            int i0 = i00[k];
            float acc = 0.0f;
            if (w00[k] != 0.0f) acc += w00[k] * __ldg(p + i0);
            if (w01[k] != 0.0f) acc += w01[k] * __ldg(p + i0 + 1);
            if (w10[k] != 0.0f) acc += w10[k] * __ldg(p + i0 + WW);
            if (w11[k] != 0.0f) acc += w11[k] * __ldg(p + i0 + WW + 1);
            v[k] = acc;
        }
        float* oc = ob + (size_t)c * HH * WW;
#pragma unroll
        for (int k = 0; k < PX; k++)
            oc[32 * k] = v[k];
    }
}

extern "C" void kernel_launch(void* const* d_in, const int* in_sizes, int n_in,
                              void* d_out, int out_size) {
    const float* x      = (const float*)d_in[0];
    const float* thetas = (const float*)d_in[1];
    const float* l1s    = (const float*)d_in[2];
    const float* l2s    = (const float*)d_in[3];
    float* out = (float*)d_out;

    compute_theta_kernel<<<1, BB>>>(thetas, l1s, l2s);

    dim3 block(32, 8, 1);
    dim3 grid(WW / (32 * PX), HH / 8, BB);   // 4 x 64 x 32 = 8192 CTAs
    warp_kernel<<<grid, block>>>(x, out);
}